// round 8
// baseline (speedup 1.0000x reference)
#include <cuda_runtime.h>
#include <cstdint>

#define BH  32
#define T   8192
#define DH  64
#define BSZ 128
#define NB  64
#define HH  4

// ---------------- scratch ----------------
__device__ float g_qsum  [BH*NB*DH];
__device__ float g_ksum  [BH*NB*DH];
__device__ float g_W     [BH*NB*DH];
__device__ float g_qfirst[BH*NB*DH];
__device__ int   g_sel   [BH*NB];
__device__ float g_wgt   [BH*NB];

__device__ __forceinline__ int rot_idx(int g, bool special) {
    return special ? ((g + BSZ - 1) & (T - 1)) : g;
}
__device__ __forceinline__ float rna_tf32(float x) {
    float r;
    asm("cvt.rna.tf32.f32 %0, %1;" : "=r"(*(uint32_t*)&r) : "f"(x));
    return r;
}
__device__ __forceinline__ void mma_tf32(float c[4], float a0, float a1,
                                         float a2, float a3,
                                         float b0, float b1) {
    asm("mma.sync.aligned.m16n8k8.row.col.f32.tf32.tf32.f32 "
        "{%0,%1,%2,%3}, {%4,%5,%6,%7}, {%8,%9}, {%0,%1,%2,%3};"
        : "+f"(c[0]), "+f"(c[1]), "+f"(c[2]), "+f"(c[3])
        : "r"(__float_as_uint(a0)), "r"(__float_as_uint(a1)),
          "r"(__float_as_uint(a2)), "r"(__float_as_uint(a3)),
          "r"(__float_as_uint(b0)), "r"(__float_as_uint(b1)));
}

// smem float-offsets (fragment-major layouts)
#define FSTR 68                         // row stride: 64 data + 4 pad
#define KOFF 0
#define VOFF (128 * FSTR)               // 8704
#define POFF (2 * 128 * FSTR)           // 17408
#define PSTR 36                         // 32 + 4 pad
#define SMEM_F (POFF + 128 * PSTR)      // 22016 floats = 88064 B

// ---------------- K1: per-bucket stats (2 buckets / block) ----------------
// W = sum_j prefix_k(j) * rinv(j) decomposed over 4 independent quarters:
//   W = sum_q [ runk_before_q * H_q + W_q ]   (breaks the serial chain; 4x MLP)
__global__ void k_bucket_stats(const float* __restrict__ q,
                               const float* __restrict__ k)
{
    __shared__ float rinv[2][BSZ];
    int ty = threadIdx.y;
    int bh = blockIdx.x >> 5;
    int u  = ((blockIdx.x & 31) << 1) + ty;
    int d  = threadIdx.x;
    bool special = ((bh & 7) >= HH);
    const float* qb = q + (size_t)bh * T * DH;
    const float* kb = k + (size_t)bh * T * DH;
    int base = u * BSZ;

    for (int j = d; j < BSZ; j += 64) rinv[ty][j] = 1.0f / (float)(base + j + 1);
    __syncthreads();

    float sumq = 0.f, qfirst = 0.f;
    float rk[4] = {0.f, 0.f, 0.f, 0.f};
    float wl[4] = {0.f, 0.f, 0.f, 0.f};
    float hq[4] = {0.f, 0.f, 0.f, 0.f};

    #pragma unroll 4
    for (int jj = 0; jj < 32; ++jj) {
        #pragma unroll
        for (int qd = 0; qd < 4; ++qd) {
            int j   = qd * 32 + jj;
            int src = rot_idx(base + j, special);
            float qv = qb[(size_t)src * DH + d];
            float kv = kb[(size_t)src * DH + d];
            if (qd == 0 && jj == 0) qfirst = qv;
            sumq += qv;
            float ri = rinv[ty][j];
            rk[qd] += kv;
            wl[qd]  = fmaf(rk[qd], ri, wl[qd]);
            hq[qd] += ri;
        }
    }

    float runk01 = rk[0] + rk[1];
    float W = wl[0]
            + fmaf(rk[0],            hq[1], wl[1])
            + fmaf(runk01,           hq[2], wl[2])
            + fmaf(runk01 + rk[2],   hq[3], wl[3]);
    float runk = runk01 + rk[2] + rk[3];

    int o = (bh * NB + u) * DH + d;
    g_qsum[o] = sumq; g_ksum[o] = runk; g_W[o] = W; g_qfirst[o] = qfirst;
}

// ---------------- K2: merged prefix + routing ----------------
__global__ void k_route2()
{
    __shared__ float sH[NB];
    __shared__ float s_sq[NB][DH + 1];
    __shared__ float s_sk[NB][DH + 1];
    int bh = blockIdx.x;
    int d  = threadIdx.x;      // 0..63
    {
        int u = d;
        float hsum = 0.f;
        for (int j = 1; j <= BSZ; ++j) hsum += 1.0f / (float)(u * BSZ + j);
        sH[u] = hsum;
    }
    __syncthreads();

    float prefQ = 0.f, prefK = 0.f;
    for (int uu = 0; uu < NB; ++uu) {
        int o = (bh * NB + uu) * DH + d;
        float qs = g_qsum[o], ks = g_ksum[o], wv = g_W[o], qf = g_qfirst[o];
        s_sq[uu][d] = (prefQ + qf) / (float)(uu * BSZ + 1);
        s_sk[uu][d] = prefK * sH[uu] + wv;
        prefQ += qs; prefK += ks;
    }
    __syncthreads();

    int u = d;
    float lg[NB + 1];
    lg[0] = 0.f;
    for (int vv = 1; vv <= u; ++vv) {
        float s = 0.f;
        #pragma unroll 8
        for (int dd = 0; dd < DH; ++dd) s += s_sq[u][dd] * s_sk[vv - 1][dd];
        lg[vv] = s * 0.125f;
    }
    if (u == 0) { g_sel[bh * NB] = 0; g_wgt[bh * NB] = 0.f; return; }
    float m = 0.f;
    for (int vv = 1; vv <= u; ++vv) m = fmaxf(m, lg[vv]);
    float ssum = 0.f;
    for (int vv = 0; vv <= u; ++vv) ssum += expf(lg[vv] - m);
    int best = 0; float bl = lg[0];
    for (int vv = 1; vv <= u - 1; ++vv)
        if (lg[vv] > bl) { bl = lg[vv]; best = vv; }
    g_sel[bh * NB + u] = best;
    g_wgt[bh * NB + u] = expf(bl - m) / ssum;
}

// ---------------- K4: mma.sync tf32 attention tile ----------------
__global__ void __launch_bounds__(256, 2)
k_attn_mma(const float* __restrict__ q, const float* __restrict__ k,
           const float* __restrict__ v, const float* __restrict__ nk,
           const float* __restrict__ nv, float* __restrict__ out)
{
    extern __shared__ float sf[];
    float* K2 = sf + KOFF;
    float* V2 = sf + VOFF;
    float* Pf = sf + POFF;

    int tid  = threadIdx.x;
    int wid  = tid >> 5, lane = tid & 31;
    int g    = lane >> 2, t = lane & 3;
    int R0   = wid * 16;
    int i0   = R0 + g, i1 = R0 + g + 8;

    int blk = blockIdx.x, bh = blk >> 6, u = blk & 63, h = bh & 7;
    bool special = (h >= HH);
    bool smask   = special && (u == NB - 1);

    int   selv = g_sel[bh * NB + u];
    float w    = g_wgt[bh * NB + u];
    const float* qb = q + (size_t)bh * T * DH;
    const float* kb = k + (size_t)bh * T * DH;
    const float* vb = v + (size_t)bh * T * DH;

    // scatter a float4 (row r, cols c0..c0+3) into fragment-major layout
    #define PUT_FRAG(buf, r, c0, val) {                                   \
        int _b = (r) * FSTR + ((c0) >> 3);                                \
        int _r8 = ((c0) & 7) * 8;                                         \
        (buf)[_b + _r8     ] = (val).x;                                   \
        (buf)[_b + _r8 + 8 ] = (val).y;                                   \
        (buf)[_b + _r8 + 16] = (val).z;                                   \
        (buf)[_b + _r8 + 24] = (val).w;                                   \
    }

    // ---- stage Q (x0.125, rna) fragment-major into K2 ----
    for (int idx = tid; idx < 128 * 16; idx += 256) {
        int r = idx >> 4, c0 = (idx & 15) * 4;
        int src = rot_idx(u * BSZ + r, special);
        float4 qq = reinterpret_cast<const float4*>(qb + (size_t)src * DH)[c0 >> 2];
        float4 o4;
        o4.x = rna_tf32(qq.x * 0.125f); o4.y = rna_tf32(qq.y * 0.125f);
        o4.z = rna_tf32(qq.z * 0.125f); o4.w = rna_tf32(qq.w * 0.125f);
        PUT_FRAG(K2, r, c0, o4);
    }
    __syncthreads();

    // ---- extract Q fragments to registers ----
    float qa0[8], qa1[8], qa2[8], qa3[8];
    {
        float4 x;
        x = *reinterpret_cast<float4*>(&K2[i0 * FSTR + t * 8]);
        qa0[0]=x.x; qa0[1]=x.y; qa0[2]=x.z; qa0[3]=x.w;
        x = *reinterpret_cast<float4*>(&K2[i0 * FSTR + t * 8 + 4]);
        qa0[4]=x.x; qa0[5]=x.y; qa0[6]=x.z; qa0[7]=x.w;
        x = *reinterpret_cast<float4*>(&K2[i1 * FSTR + t * 8]);
        qa1[0]=x.x; qa1[1]=x.y; qa1[2]=x.z; qa1[3]=x.w;
        x = *reinterpret_cast<float4*>(&K2[i1 * FSTR + t * 8 + 4]);
        qa1[4]=x.x; qa1[5]=x.y; qa1[6]=x.z; qa1[7]=x.w;
        x = *reinterpret_cast<float4*>(&K2[i0 * FSTR + (t + 4) * 8]);
        qa2[0]=x.x; qa2[1]=x.y; qa2[2]=x.z; qa2[3]=x.w;
        x = *reinterpret_cast<float4*>(&K2[i0 * FSTR + (t + 4) * 8 + 4]);
        qa2[4]=x.x; qa2[5]=x.y; qa2[6]=x.z; qa2[7]=x.w;
        x = *reinterpret_cast<float4*>(&K2[i1 * FSTR + (t + 4) * 8]);
        qa3[0]=x.x; qa3[1]=x.y; qa3[2]=x.z; qa3[3]=x.w;
        x = *reinterpret_cast<float4*>(&K2[i1 * FSTR + (t + 4) * 8 + 4]);
        qa3[4]=x.x; qa3[5]=x.y; qa3[6]=x.z; qa3[7]=x.w;
    }

    float oacc[8][4];
    #pragma unroll
    for (int n = 0; n < 8; ++n)
        #pragma unroll
        for (int m = 0; m < 4; ++m) oacc[n][m] = 0.f;
    float lsum0 = 0.f, lsum1 = 0.f;

    for (int phase = 0; phase < 2; ++phase) {
        __syncthreads();   // previous readers of K2/V2 done

        // ---- stage K/V for this phase (fragment-major) ----
        for (int idx = tid; idx < 128 * 16; idx += 256) {
            int r = idx >> 4, c0 = (idx & 15) * 4;
            float4 kk, vv;
            if (phase == 0) {
                if (selv == 0) {
                    kk = reinterpret_cast<const float4*>(nk + h * DH)[c0 >> 2];
                    vv = reinterpret_cast<const float4*>(nv + h * DH)[c0 >> 2];
                } else {
                    int src = rot_idx((selv - 1) * BSZ + r, special);
                    kk = reinterpret_cast<const float4*>(kb + (size_t)src * DH)[c0 >> 2];
                    vv = reinterpret_cast<const float4*>(vb + (size_t)src * DH)[c0 >> 2];
                }
                kk.x *= w; kk.y *= w; kk.z *= w; kk.w *= w;
                vv.x *= w; vv.y *= w; vv.z *= w; vv.w *= w;
            } else {
                int src = rot_idx(u * BSZ + r, special);
                kk = reinterpret_cast<const float4*>(kb + (size_t)src * DH)[c0 >> 2];
                vv = reinterpret_cast<const float4*>(vb + (size_t)src * DH)[c0 >> 2];
            }
            float4 k4, v4;
            k4.x = rna_tf32(kk.x); k4.y = rna_tf32(kk.y);
            k4.z = rna_tf32(kk.z); k4.w = rna_tf32(kk.w);
            v4.x = rna_tf32(vv.x); v4.y = rna_tf32(vv.y);
            v4.z = rna_tf32(vv.z); v4.w = rna_tf32(vv.w);
            PUT_FRAG(K2, r, c0, k4);
            PUT_FRAG(V2, r, c0, v4);
        }
        __syncthreads();

        // strips needed by this warp this phase
        int smax;
        if (phase == 0) smax = (smask && wid > 0) ? -1 : 3;
        else            smax = (R0 + 15) >> 5;

        for (int s = 0; s <= smax; ++s) {
            float c4[4][4];
            #pragma unroll
            for (int n = 0; n < 4; ++n)
                #pragma unroll
                for (int m = 0; m < 4; ++m) c4[n][m] = 0.f;

            // ---- QK: S[16, 32] ----
            #pragma unroll
            for (int nt = 0; nt < 4; ++nt) {
                int j = s * 32 + nt * 8 + g;
                float4 b0lo = *reinterpret_cast<float4*>(&K2[j * FSTR + t * 8]);
                float4 b0hi = *reinterpret_cast<float4*>(&K2[j * FSTR + t * 8 + 4]);
                float4 b1lo = *reinterpret_cast<float4*>(&K2[j * FSTR + (t + 4) * 8]);
                float4 b1hi = *reinterpret_cast<float4*>(&K2[j * FSTR + (t + 4) * 8 + 4]);
                mma_tf32(c4[nt], qa0[0], qa1[0], qa2[0], qa3[0], b0lo.x, b1lo.x);
                mma_tf32(c4[nt], qa0[1], qa1[1], qa2[1], qa3[1], b0lo.y, b1lo.y);
                mma_tf32(c4[nt], qa0[2], qa1[2], qa2[2], qa3[2], b0lo.z, b1lo.z);
                mma_tf32(c4[nt], qa0[3], qa1[3], qa2[3], qa3[3], b0lo.w, b1lo.w);
                mma_tf32(c4[nt], qa0[4], qa1[4], qa2[4], qa3[4], b0hi.x, b1hi.x);
                mma_tf32(c4[nt], qa0[5], qa1[5], qa2[5], qa3[5], b0hi.y, b1hi.y);
                mma_tf32(c4[nt], qa0[6], qa1[6], qa2[6], qa3[6], b0hi.z, b1hi.z);
                mma_tf32(c4[nt], qa0[7], qa1[7], qa2[7], qa3[7], b0hi.w, b1hi.w);
            }

            __syncwarp();   // prior strip's P loads complete

            // ---- epilogue: mask + exp + row-sums + store P ----
            bool full = (phase == 1) && (s < smax) && !(smask && s == 0);
            #pragma unroll
            for (int nt = 0; nt < 4; ++nt) {
                int jb = s * 32 + nt * 8 + 2 * t;
                #pragma unroll
                for (int m = 0; m < 4; ++m) {
                    float p;
                    if (full) {
                        p = __expf(fminf(c4[nt][m], 80.f));
                    } else {
                        int row = (m < 2) ? i0 : i1;
                        int jc  = jb + (m & 1);
                        bool ok;
                        if (phase == 0) ok = (!smask) || (row == 0);
                        else ok = smask ? (row == 0 ? (jc == 0)
                                                    : (jc >= 1 && jc <= row))
                                        : (jc <= row);
                        p = ok ? __expf(fminf(c4[nt][m], 80.f)) : 0.f;
                    }
                    if (m < 2) lsum0 += p; else lsum1 += p;
                    c4[nt][m] = rna_tf32(p);
                }
                Pf[i0 * PSTR + 8 * t     + nt] = c4[nt][0];
                Pf[i0 * PSTR + 8 * t + 4 + nt] = c4[nt][1];
                Pf[i1 * PSTR + 8 * t     + nt] = c4[nt][2];
                Pf[i1 * PSTR + 8 * t + 4 + nt] = c4[nt][3];
            }
            __syncwarp();

            // ---- PV: O[16, 64] += P[16, 32] * V[32, 64] ----
            float4 pa0 = *reinterpret_cast<float4*>(&Pf[i0 * PSTR + t * 4]);
            float4 pa1 = *reinterpret_cast<float4*>(&Pf[i1 * PSTR + t * 4]);
            float4 pa2 = *reinterpret_cast<float4*>(&Pf[i0 * PSTR + (t + 4) * 4]);
            float4 pa3 = *reinterpret_cast<float4*>(&Pf[i1 * PSTR + (t + 4) * 4]);
            float a0v[4] = {pa0.x, pa0.y, pa0.z, pa0.w};
            float a1v[4] = {pa1.x, pa1.y, pa1.z, pa1.w};
            float a2v[4] = {pa2.x, pa2.y, pa2.z, pa2.w};
            float a3v[4] = {pa3.x, pa3.y, pa3.z, pa3.w};

            #pragma unroll
            for (int kt2 = 0; kt2 < 4; ++kt2) {
                int jr = s * 32 + kt2 * 8;
                float4 v0lo = *reinterpret_cast<float4*>(&V2[(jr + t) * FSTR + g * 8]);
                float4 v0hi = *reinterpret_cast<float4*>(&V2[(jr + t) * FSTR + g * 8 + 4]);
                float4 v1lo = *reinterpret_cast<float4*>(&V2[(jr + t + 4) * FSTR + g * 8]);
                float4 v1hi = *reinterpret_cast<float4*>(&V2[(jr + t + 4) * FSTR + g * 8 + 4]);
                float a0 = a0v[kt2], a1 = a1v[kt2], a2 = a2v[kt2], a3 = a3v[kt2];
                mma_tf32(oacc[0], a0, a1, a2, a3, v0lo.x, v1lo.x);
                mma_tf32(oacc[1], a0, a1, a2, a3, v0lo.y, v1lo.y);
                mma_tf32(oacc[2], a0, a1, a2, a3, v0lo.z, v1lo.z);
                mma_tf32(oacc[3], a0, a1, a2, a3, v0lo.w, v1lo.w);
                mma_tf32(oacc[4], a0, a1, a2, a3, v0hi.x, v1hi.x);
                mma_tf32(oacc[5], a0, a1, a2, a3, v0hi.y, v1hi.y);
                mma_tf32(oacc[6], a0, a1, a2, a3, v0hi.z, v1hi.z);
                mma_tf32(oacc[7], a0, a1, a2, a3, v0hi.w, v1hi.w);
            }
        }
    }

    // ---- row-sum reduction across the 4 lanes of each row group ----
    lsum0 += __shfl_xor_sync(0xFFFFFFFFu, lsum0, 1);
    lsum0 += __shfl_xor_sync(0xFFFFFFFFu, lsum0, 2);
    lsum1 += __shfl_xor_sync(0xFFFFFFFFu, lsum1, 1);
    lsum1 += __shfl_xor_sync(0xFFFFFFFFu, lsum1, 2);
    float inv0 = 1.0f / lsum0;
    float inv1 = 1.0f / lsum1;

    // ---- write O ----
    int gr0 = rot_idx(u * BSZ + i0, special);
    int gr1 = rot_idx(u * BSZ + i1, special);
    float* op0 = out + ((size_t)bh * T + gr0) * DH;
    float* op1 = out + ((size_t)bh * T + gr1) * DH;
    #pragma unroll
    for (int nt = 0; nt < 8; ++nt) {
        int col = nt * 8 + 2 * t;
        *reinterpret_cast<float2*>(op0 + col) =
            make_float2(oacc[nt][0] * inv0, oacc[nt][1] * inv0);
        *reinterpret_cast<float2*>(op1 + col) =
            make_float2(oacc[nt][2] * inv1, oacc[nt][3] * inv1);
    }
    #undef PUT_FRAG
}

// ---------------- launch ----------------
extern "C" void kernel_launch(void* const* d_in, const int* in_sizes, int n_in,
                              void* d_out, int out_size)
{
    (void)in_sizes; (void)n_in; (void)out_size;
    const float* q  = (const float*)d_in[0];
    const float* k  = (const float*)d_in[1];
    const float* v  = (const float*)d_in[2];
    const float* nk = (const float*)d_in[3];
    const float* nv = (const float*)d_in[4];
    float* out = (float*)d_out;

    const int smem = SMEM_F * (int)sizeof(float);   // 88064 B
    cudaFuncSetAttribute(k_attn_mma, cudaFuncAttributeMaxDynamicSharedMemorySize, smem);

    dim3 bs_blk(64, 2);
    k_bucket_stats<<<BH * 32, bs_blk>>>(q, k);
    k_route2<<<BH, DH>>>();
    k_attn_mma<<<BH * NB, 256, smem>>>(q, k, v, nk, nv, out);
}

// round 9
// speedup vs baseline: 1.1368x; 1.1368x over previous
#include <cuda_runtime.h>
#include <cstdint>

#define BH  32
#define T   8192
#define DH  64
#define BSZ 128
#define NB  64
#define HH  4

// ---------------- scratch ----------------
__device__ float g_qsum  [BH*NB*DH];
__device__ float g_ksum  [BH*NB*DH];
__device__ float g_W     [BH*NB*DH];
__device__ float g_qfirst[BH*NB*DH];
__device__ int   g_sel   [BH*NB];
__device__ float g_wgt   [BH*NB];

__device__ __forceinline__ int rot_idx(int g, bool special) {
    return special ? ((g + BSZ - 1) & (T - 1)) : g;
}
__device__ __forceinline__ float rna_tf32(float x) {
    float r;
    asm("cvt.rna.tf32.f32 %0, %1;" : "=r"(*(uint32_t*)&r) : "f"(x));
    return r;
}
__device__ __forceinline__ void mma_tf32(float c[4], float a0, float a1,
                                         float a2, float a3,
                                         float b0, float b1) {
    asm("mma.sync.aligned.m16n8k8.row.col.f32.tf32.tf32.f32 "
        "{%0,%1,%2,%3}, {%4,%5,%6,%7}, {%8,%9}, {%0,%1,%2,%3};"
        : "+f"(c[0]), "+f"(c[1]), "+f"(c[2]), "+f"(c[3])
        : "r"(__float_as_uint(a0)), "r"(__float_as_uint(a1)),
          "r"(__float_as_uint(a2)), "r"(__float_as_uint(a3)),
          "r"(__float_as_uint(b0)), "r"(__float_as_uint(b1)));
}

// smem float-offsets (fragment-major layouts)
#define FSTR 68                         // row stride: 64 data + 4 pad
#define QOFF 0
#define KOFF (128 * FSTR)               // 8704
#define VOFF (256 * FSTR)               // 17408
#define SMEM_F (384 * FSTR)             // 26112 floats = 104448 B

// ---------------- K1: per-bucket stats (2 buckets / block) ----------------
__global__ void k_bucket_stats(const float* __restrict__ q,
                               const float* __restrict__ k)
{
    __shared__ float rinv[2][BSZ];
    int ty = threadIdx.y;
    int bh = blockIdx.x >> 5;
    int u  = ((blockIdx.x & 31) << 1) + ty;
    int d  = threadIdx.x;
    bool special = ((bh & 7) >= HH);
    const float* qb = q + (size_t)bh * T * DH;
    const float* kb = k + (size_t)bh * T * DH;
    int base = u * BSZ;

    for (int j = d; j < BSZ; j += 64) rinv[ty][j] = 1.0f / (float)(base + j + 1);
    __syncthreads();

    float runk = 0.f, W = 0.f, sumq = 0.f, qfirst = 0.f;
    #pragma unroll 8
    for (int j = 0; j < BSZ; ++j) {
        int src = rot_idx(base + j, special);
        float qv = qb[(size_t)src * DH + d];
        float kv = kb[(size_t)src * DH + d];
        if (j == 0) qfirst = qv;
        sumq += qv;
        runk += kv;
        W = fmaf(runk, rinv[ty][j], W);
    }
    int o = (bh * NB + u) * DH + d;
    g_qsum[o] = sumq; g_ksum[o] = runk; g_W[o] = W; g_qfirst[o] = qfirst;
}

// ---------------- K2: merged prefix + routing ----------------
__global__ void k_route2()
{
    __shared__ float sH[NB];
    __shared__ float s_sq[NB][DH + 1];
    __shared__ float s_sk[NB][DH + 1];
    int bh = blockIdx.x;
    int d  = threadIdx.x;      // 0..63
    {
        int u = d;
        float hsum = 0.f;
        for (int j = 1; j <= BSZ; ++j) hsum += 1.0f / (float)(u * BSZ + j);
        sH[u] = hsum;
    }
    __syncthreads();

    float prefQ = 0.f, prefK = 0.f;
    for (int uu = 0; uu < NB; ++uu) {
        int o = (bh * NB + uu) * DH + d;
        float qs = g_qsum[o], ks = g_ksum[o], wv = g_W[o], qf = g_qfirst[o];
        s_sq[uu][d] = (prefQ + qf) / (float)(uu * BSZ + 1);
        s_sk[uu][d] = prefK * sH[uu] + wv;
        prefQ += qs; prefK += ks;
    }
    __syncthreads();

    int u = d;
    float lg[NB + 1];
    lg[0] = 0.f;
    for (int vv = 1; vv <= u; ++vv) {
        float s = 0.f;
        #pragma unroll 8
        for (int dd = 0; dd < DH; ++dd) s += s_sq[u][dd] * s_sk[vv - 1][dd];
        lg[vv] = s * 0.125f;
    }
    if (u == 0) { g_sel[bh * NB] = 0; g_wgt[bh * NB] = 0.f; return; }
    float m = 0.f;
    for (int vv = 1; vv <= u; ++vv) m = fmaxf(m, lg[vv]);
    float ssum = 0.f;
    for (int vv = 0; vv <= u; ++vv) ssum += expf(lg[vv] - m);
    int best = 0; float bl = lg[0];
    for (int vv = 1; vv <= u - 1; ++vv)
        if (lg[vv] > bl) { bl = lg[vv]; best = vv; }
    g_sel[bh * NB + u] = best;
    g_wgt[bh * NB + u] = expf(bl - m) / ssum;
}

// ---------------- K4: mma.sync tf32 attention tile (v4) ----------------
// 256 threads = 8 warps; warp w owns Q rows [16w, 16w+16).
// Q dedicated smem region; Q+K_A+V_A staged in ONE pass (one barrier).
// P never touches smem: S->A fragment conversion via shfl.idx permutation.
__global__ void __launch_bounds__(256, 2)
k_attn_mma(const float* __restrict__ q, const float* __restrict__ k,
           const float* __restrict__ v, const float* __restrict__ nk,
           const float* __restrict__ nv, float* __restrict__ out)
{
    extern __shared__ float sf[];
    float* Qs = sf + QOFF;
    float* K2 = sf + KOFF;
    float* V2 = sf + VOFF;

    int tid  = threadIdx.x;
    int wid  = tid >> 5, lane = tid & 31;
    int g    = lane >> 2, t = lane & 3;
    int R0   = wid * 16;
    int i0   = R0 + g, i1 = R0 + g + 8;

    int blk = blockIdx.x, bh = blk >> 6, u = blk & 63, h = bh & 7;
    bool special = (h >= HH);
    bool smask   = special && (u == NB - 1);

    int   selv = g_sel[bh * NB + u];
    float w    = g_wgt[bh * NB + u];
    const float* qb = q + (size_t)bh * T * DH;
    const float* kb = k + (size_t)bh * T * DH;
    const float* vb = v + (size_t)bh * T * DH;

    // scatter a float4 (row r, cols c0..c0+3) into fragment-major layout
    #define PUT_FRAG(buf, r, c0, val) {                                   \
        int _b = (r) * FSTR + ((c0) >> 3);                                \
        int _r8 = ((c0) & 7) * 8;                                         \
        (buf)[_b + _r8     ] = (val).x;                                   \
        (buf)[_b + _r8 + 8 ] = (val).y;                                   \
        (buf)[_b + _r8 + 16] = (val).z;                                   \
        (buf)[_b + _r8 + 24] = (val).w;                                   \
    }

    // ---- merged stage: Q (x0.125, rna) + K_A/V_A (weighted, rna) ----
    for (int idx = tid; idx < 128 * 16; idx += 256) {
        int r = idx >> 4, c0 = (idx & 15) * 4;
        int srcQ = rot_idx(u * BSZ + r, special);
        float4 qq = reinterpret_cast<const float4*>(qb + (size_t)srcQ * DH)[c0 >> 2];
        float4 kk, vv;
        if (selv == 0) {
            kk = reinterpret_cast<const float4*>(nk + h * DH)[c0 >> 2];
            vv = reinterpret_cast<const float4*>(nv + h * DH)[c0 >> 2];
        } else {
            int srcA = rot_idx((selv - 1) * BSZ + r, special);
            kk = reinterpret_cast<const float4*>(kb + (size_t)srcA * DH)[c0 >> 2];
            vv = reinterpret_cast<const float4*>(vb + (size_t)srcA * DH)[c0 >> 2];
        }
        float4 q4, k4, v4;
        q4.x = rna_tf32(qq.x * 0.125f); q4.y = rna_tf32(qq.y * 0.125f);
        q4.z = rna_tf32(qq.z * 0.125f); q4.w = rna_tf32(qq.w * 0.125f);
        k4.x = rna_tf32(kk.x * w); k4.y = rna_tf32(kk.y * w);
        k4.z = rna_tf32(kk.z * w); k4.w = rna_tf32(kk.w * w);
        v4.x = rna_tf32(vv.x * w); v4.y = rna_tf32(vv.y * w);
        v4.z = rna_tf32(vv.z * w); v4.w = rna_tf32(vv.w * w);
        PUT_FRAG(Qs, r, c0, q4);
        PUT_FRAG(K2, r, c0, k4);
        PUT_FRAG(V2, r, c0, v4);
    }
    __syncthreads();

    // ---- extract Q fragments to registers ----
    float qa0[8], qa1[8], qa2[8], qa3[8];
    {
        float4 x;
        x = *reinterpret_cast<float4*>(&Qs[i0 * FSTR + t * 8]);
        qa0[0]=x.x; qa0[1]=x.y; qa0[2]=x.z; qa0[3]=x.w;
        x = *reinterpret_cast<float4*>(&Qs[i0 * FSTR + t * 8 + 4]);
        qa0[4]=x.x; qa0[5]=x.y; qa0[6]=x.z; qa0[7]=x.w;
        x = *reinterpret_cast<float4*>(&Qs[i1 * FSTR + t * 8]);
        qa1[0]=x.x; qa1[1]=x.y; qa1[2]=x.z; qa1[3]=x.w;
        x = *reinterpret_cast<float4*>(&Qs[i1 * FSTR + t * 8 + 4]);
        qa1[4]=x.x; qa1[5]=x.y; qa1[6]=x.z; qa1[7]=x.w;
        x = *reinterpret_cast<float4*>(&Qs[i0 * FSTR + (t + 4) * 8]);
        qa2[0]=x.x; qa2[1]=x.y; qa2[2]=x.z; qa2[3]=x.w;
        x = *reinterpret_cast<float4*>(&Qs[i0 * FSTR + (t + 4) * 8 + 4]);
        qa2[4]=x.x; qa2[5]=x.y; qa2[6]=x.z; qa2[7]=x.w;
        x = *reinterpret_cast<float4*>(&Qs[i1 * FSTR + (t + 4) * 8]);
        qa3[0]=x.x; qa3[1]=x.y; qa3[2]=x.z; qa3[3]=x.w;
        x = *reinterpret_cast<float4*>(&Qs[i1 * FSTR + (t + 4) * 8 + 4]);
        qa3[4]=x.x; qa3[5]=x.y; qa3[6]=x.z; qa3[7]=x.w;
    }

    float oacc[8][4];
    #pragma unroll
    for (int n = 0; n < 8; ++n)
        #pragma unroll
        for (int m = 0; m < 4; ++m) oacc[n][m] = 0.f;
    float lsum0 = 0.f, lsum1 = 0.f;

    int srcA = (lane & 28) | (t >> 1);   // 4g + t/2
    int srcB = srcA + 2;

    // ================= strip body =================
    #define STRIP(PHASE, S)                                                   \
    {                                                                         \
        float c4[4][4];                                                       \
        _Pragma("unroll")                                                     \
        for (int n = 0; n < 4; ++n)                                           \
            _Pragma("unroll")                                                 \
            for (int m = 0; m < 4; ++m) c4[n][m] = 0.f;                       \
        /* QK: S[16,32] */                                                    \
        _Pragma("unroll")                                                     \
        for (int nt = 0; nt < 4; ++nt) {                                      \
            int j = (S) * 32 + nt * 8 + g;                                    \
            float4 b0lo = *reinterpret_cast<float4*>(&K2[j * FSTR + t * 8]);  \
            float4 b0hi = *reinterpret_cast<float4*>(&K2[j * FSTR + t * 8 + 4]); \
            float4 b1lo = *reinterpret_cast<float4*>(&K2[j * FSTR + (t + 4) * 8]); \
            float4 b1hi = *reinterpret_cast<float4*>(&K2[j * FSTR + (t + 4) * 8 + 4]); \
            mma_tf32(c4[nt], qa0[0], qa1[0], qa2[0], qa3[0], b0lo.x, b1lo.x); \
            mma_tf32(c4[nt], qa0[1], qa1[1], qa2[1], qa3[1], b0lo.y, b1lo.y); \
            mma_tf32(c4[nt], qa0[2], qa1[2], qa2[2], qa3[2], b0lo.z, b1lo.z); \
            mma_tf32(c4[nt], qa0[3], qa1[3], qa2[3], qa3[3], b0lo.w, b1lo.w); \
            mma_tf32(c4[nt], qa0[4], qa1[4], qa2[4], qa3[4], b0hi.x, b1hi.x); \
            mma_tf32(c4[nt], qa0[5], qa1[5], qa2[5], qa3[5], b0hi.y, b1hi.y); \
            mma_tf32(c4[nt], qa0[6], qa1[6], qa2[6], qa3[6], b0hi.z, b1hi.z); \
            mma_tf32(c4[nt], qa0[7], qa1[7], qa2[7], qa3[7], b0hi.w, b1hi.w); \
        }                                                                     \
        /* epilogue: mask + exp + row-sums (P stays in registers) */          \
        _Pragma("unroll")                                                     \
        for (int nt = 0; nt < 4; ++nt) {                                      \
            int jb = (S) * 32 + nt * 8 + 2 * t;                               \
            _Pragma("unroll")                                                 \
            for (int m = 0; m < 4; ++m) {                                     \
                int row = (m < 2) ? i0 : i1;                                  \
                int jc  = jb + (m & 1);                                       \
                bool ok;                                                      \
                if ((PHASE) == 0) ok = (!smask) || (row == 0);                \
                else ok = smask ? (row == 0 ? (jc == 0)                       \
                                            : (jc >= 1 && jc <= row))         \
                                : (jc <= row);                                \
                float p = ok ? __expf(fminf(c4[nt][m], 80.f)) : 0.f;          \
                if (m < 2) lsum0 += p; else lsum1 += p;                       \
                c4[nt][m] = rna_tf32(p);                                      \
            }                                                                 \
        }                                                                     \
        /* S-frag -> A-frag via lane permutation */                           \
        float pa0[4], pa1[4], pa2[4], pa3[4];                                 \
        _Pragma("unroll")                                                     \
        for (int kt = 0; kt < 4; ++kt) {                                      \
            float v0A = __shfl_sync(0xFFFFFFFFu, c4[kt][0], srcA);            \
            float v1A = __shfl_sync(0xFFFFFFFFu, c4[kt][1], srcA);            \
            float v2A = __shfl_sync(0xFFFFFFFFu, c4[kt][2], srcA);            \
            float v3A = __shfl_sync(0xFFFFFFFFu, c4[kt][3], srcA);            \
            float v0B = __shfl_sync(0xFFFFFFFFu, c4[kt][0], srcB);            \
            float v1B = __shfl_sync(0xFFFFFFFFu, c4[kt][1], srcB);            \
            float v2B = __shfl_sync(0xFFFFFFFFu, c4[kt][2], srcB);            \
            float v3B = __shfl_sync(0xFFFFFFFFu, c4[kt][3], srcB);            \
            bool odd = (t & 1);                                               \
            pa0[kt] = odd ? v1A : v0A;                                        \
            pa1[kt] = odd ? v3A : v2A;                                        \
            pa2[kt] = odd ? v1B : v0B;                                        \
            pa3[kt] = odd ? v3B : v2B;                                        \
        }                                                                     \
        /* PV: O[16,64] += P[16,32] * V[32,64] */                             \
        _Pragma("unroll")                                                     \
        for (int kt2 = 0; kt2 < 4; ++kt2) {                                   \
            int jr = (S) * 32 + kt2 * 8;                                      \
            float4 v0lo = *reinterpret_cast<float4*>(&V2[(jr + t) * FSTR + g * 8]); \
            float4 v0hi = *reinterpret_cast<float4*>(&V2[(jr + t) * FSTR + g * 8 + 4]); \
            float4 v1lo = *reinterpret_cast<float4*>(&V2[(jr + t + 4) * FSTR + g * 8]); \
            float4 v1hi = *reinterpret_cast<float4*>(&V2[(jr + t + 4) * FSTR + g * 8 + 4]); \
            float a0 = pa0[kt2], a1 = pa1[kt2], a2 = pa2[kt2], a3 = pa3[kt2]; \
            mma_tf32(oacc[0], a0, a1, a2, a3, v0lo.x, v1lo.x);                \
            mma_tf32(oacc[1], a0, a1, a2, a3, v0lo.y, v1lo.y);                \
            mma_tf32(oacc[2], a0, a1, a2, a3, v0lo.z, v1lo.z);                \
            mma_tf32(oacc[3], a0, a1, a2, a3, v0lo.w, v1lo.w);                \
            mma_tf32(oacc[4], a0, a1, a2, a3, v0hi.x, v1hi.x);                \
            mma_tf32(oacc[5], a0, a1, a2, a3, v0hi.y, v1hi.y);                \
            mma_tf32(oacc[6], a0, a1, a2, a3, v0hi.z, v1hi.z);                \
            mma_tf32(oacc[7], a0, a1, a2, a3, v0hi.w, v1hi.w);                \
        }                                                                     \
    }
    // ==============================================

    // ---- phase A (routed keys) ----
    {
        int smaxA = (smask && wid > 0) ? -1 : 3;
        for (int s = 0; s <= smaxA; ++s) STRIP(0, s);
    }
    __syncthreads();

    // ---- stage K_B/V_B (own bucket) ----
    for (int idx = tid; idx < 128 * 16; idx += 256) {
        int r = idx >> 4, c0 = (idx & 15) * 4;
        int src = rot_idx(u * BSZ + r, special);
        float4 kk = reinterpret_cast<const float4*>(kb + (size_t)src * DH)[c0 >> 2];
        float4 vv = reinterpret_cast<const float4*>(vb + (size_t)src * DH)[c0 >> 2];
        float4 k4, v4;
        k4.x = rna_tf32(kk.x); k4.y = rna_tf32(kk.y);
        k4.z = rna_tf32(kk.z); k4.w = rna_tf32(kk.w);
        v4.x = rna_tf32(vv.x); v4.y = rna_tf32(vv.y);
        v4.z = rna_tf32(vv.z); v4.w = rna_tf32(vv.w);
        PUT_FRAG(K2, r, c0, k4);
        PUT_FRAG(V2, r, c0, v4);
    }
    __syncthreads();

    // ---- phase B (own keys, triangular) ----
    {
        int smaxB = (R0 + 15) >> 5;
        for (int s = 0; s <= smaxB; ++s) STRIP(1, s);
    }
    #undef STRIP
    #undef PUT_FRAG

    // ---- row-sum reduction across the 4 lanes of each row group ----
    lsum0 += __shfl_xor_sync(0xFFFFFFFFu, lsum0, 1);
    lsum0 += __shfl_xor_sync(0xFFFFFFFFu, lsum0, 2);
    lsum1 += __shfl_xor_sync(0xFFFFFFFFu, lsum1, 1);
    lsum1 += __shfl_xor_sync(0xFFFFFFFFu, lsum1, 2);
    float inv0 = 1.0f / lsum0;
    float inv1 = 1.0f / lsum1;

    // ---- write O ----
    int gr0 = rot_idx(u * BSZ + i0, special);
    int gr1 = rot_idx(u * BSZ + i1, special);
    float* op0 = out + ((size_t)bh * T + gr0) * DH;
    float* op1 = out + ((size_t)bh * T + gr1) * DH;
    #pragma unroll
    for (int nt = 0; nt < 8; ++nt) {
        int col = nt * 8 + 2 * t;
        *reinterpret_cast<float2*>(op0 + col) =
            make_float2(oacc[nt][0] * inv0, oacc[nt][1] * inv0);
        *reinterpret_cast<float2*>(op1 + col) =
            make_float2(oacc[nt][2] * inv1, oacc[nt][3] * inv1);
    }
}

// ---------------- launch ----------------
extern "C" void kernel_launch(void* const* d_in, const int* in_sizes, int n_in,
                              void* d_out, int out_size)
{
    (void)in_sizes; (void)n_in; (void)out_size;
    const float* q  = (const float*)d_in[0];
    const float* k  = (const float*)d_in[1];
    const float* v  = (const float*)d_in[2];
    const float* nk = (const float*)d_in[3];
    const float* nv = (const float*)d_in[4];
    float* out = (float*)d_out;

    const int smem = SMEM_F * (int)sizeof(float);   // 104448 B
    cudaFuncSetAttribute(k_attn_mma, cudaFuncAttributeMaxDynamicSharedMemorySize, smem);

    dim3 bs_blk(64, 2);
    k_bucket_stats<<<BH * 32, bs_blk>>>(q, k);
    k_route2<<<BH, DH>>>();
    k_attn_mma<<<BH * NB, 256, smem>>>(q, k, v, nk, nv, out);
}